// round 11
// baseline (speedup 1.0000x reference)
#include <cuda_runtime.h>
#include <math.h>

// Problem dims
#define BATCH 32
#define CCH   192
#define HW    4096                 // 64*64
#define NTOT  (BATCH * CCH * HW)   // 25,165,824 elements
#define N4    (NTOT / 4)           // float4 count (6,291,456)
#define LOG2E 1.4426950408889634f

__device__ __forceinline__ float softplus_fast(float x) {
    return fmaxf(x, 0.0f) + __logf(1.0f + __expf(-fabsf(x)));
}
__device__ __forceinline__ float sigmoid_acc(float x) {
    return fmaf(0.5f, tanhf(0.5f * x), 0.5f);
}
__device__ __forceinline__ float ex2_approx(float x) {
    float r; asm("ex2.approx.f32 %0, %1;" : "=f"(r) : "f"(x)); return r;
}
__device__ __forceinline__ float rcp_approx(float x) {
    float r; asm("rcp.approx.f32 %0, %1;" : "=f"(r) : "f"(x)); return r;
}

// Shared layout P[48]:
// [0:3)=sp0 [3:12)=W1 [12:21)=W2 [21:24)=w3
// [24:27)=b0 [27:30)=b1 [30:33)=b2 [33]=b3 [34:43)=RAW f0..f2
// (factors raw; tanh applied only on the cold fallback path)

// Generic full-MLP CDF (fallback; factors raw in S[34..42])
__device__ float cdf_full_raw(const float* __restrict__ S, float x) {
    float v[3], w[3];
    #pragma unroll
    for (int o = 0; o < 3; o++) {
        v[o] = fmaf(S[0 + o], x, S[24 + o]);
        v[o] = fmaf(tanhf(S[34 + o]), tanhf(v[o]), v[o]);
    }
    #pragma unroll
    for (int o = 0; o < 3; o++) {
        w[o] = S[27 + o] + S[3 + o*3 + 0]*v[0] + S[3 + o*3 + 1]*v[1] + S[3 + o*3 + 2]*v[2];
        w[o] = fmaf(tanhf(S[37 + o]), tanhf(w[o]), w[o]);
    }
    #pragma unroll
    for (int o = 0; o < 3; o++) {
        v[o] = S[30 + o] + S[12 + o*3 + 0]*w[0] + S[12 + o*3 + 1]*w[1] + S[12 + o*3 + 2]*w[2];
        v[o] = fmaf(tanhf(S[40 + o]), tanhf(v[o]), v[o]);
    }
    float s = S[33] + S[21]*v[0] + S[22]*v[1] + S[23]*v[2];
    return sigmoid_acc(s);
}

__device__ __noinline__ void fp_fallback(const float* __restrict__ S, const float4 zz,
                                         float4* zh_out, float4* lk_out) {
    float in[4] = {zz.x, zz.y, zz.z, zz.w};
    float oh[4], ol[4];
    #pragma unroll
    for (int i = 0; i < 4; i++) {
        float h  = rintf(in[i]);
        float up = cdf_full_raw(S, h + 0.5f);
        float lo = cdf_full_raw(S, h - 0.5f);
        oh[i] = h;
        ol[i] = fmaxf(up - lo, 1e-9f);
    }
    *zh_out = make_float4(oh[0], oh[1], oh[2], oh[3]);
    *lk_out = make_float4(ol[0], ol[1], ol[2], ol[3]);
}

// ---------------------------------------------------------------------------
// Single fused kernel, R4-profile hot loop (8 elems/thread, 2 front-batched
// float4 loads, 2 blocks per (b,c) slice -> channel uniform per block).
//
// Preamble: WARP 0 ONLY. Lane-parallel param load + softplus into shared
// P[48]; lane 0 composes the affine collapse logit(x)=a*x+d and publishes
// {na, nd, ea, aff} to shared. One __syncthreads. Warps 1-7 wait at the
// barrier while their z loads (issued first) are in flight -> hidden.
//
// Hot path per element:
//   h   = rint(z)                               (half-to-even == jnp.round)
//   e1  = 2^(na*h + nd)   == exp(-(a*(h+0.5)+d))
//   e2  = e1 * ea         == exp(-(logit - a))
//   lik = max((e2-e1) * rcp((1+e1)*(1+e2)), 1e-9)
// Tails: e1->inf => NaN => fmax -> 1e-9 (== clipped ref); e1->0 => 0 -> 1e-9.
// ---------------------------------------------------------------------------
__global__ void __launch_bounds__(256, 5)
fp_fused(const float* __restrict__ z, float* __restrict__ out,
         const float* __restrict__ m0, const float* __restrict__ m1,
         const float* __restrict__ m2, const float* __restrict__ m3,
         const float* __restrict__ b0, const float* __restrict__ b1,
         const float* __restrict__ b2, const float* __restrict__ b3,
         const float* __restrict__ f0, const float* __restrict__ f1,
         const float* __restrict__ f2) {
    __shared__ float P[48];
    __shared__ float4 sC;   // {na, nd, ea, aff}

    const int tid = threadIdx.x;
    const int c  = (blockIdx.x >> 1) % CCH;        // 2 blocks per (b,c) slice
    const int n4 = blockIdx.x * 512 + tid;         // first float4 index

    const float4* zin = reinterpret_cast<const float4*>(z);
    float4* o = reinterpret_cast<float4*>(out);

    // Front-batch the streaming loads; preamble + barrier hide under them.
    float4 zz0 = __ldcs(zin + n4);
    float4 zz1 = __ldcs(zin + n4 + 256);

    // ---- warp-0 preamble ----
    if (tid < 32) {
        const int lane = tid;
        float v;
        if (lane < 3)       v = softplus_fast(m0[c * 3 + lane]);
        else if (lane < 12) v = softplus_fast(m1[c * 9 + (lane - 3)]);
        else if (lane < 21) v = softplus_fast(m2[c * 9 + (lane - 12)]);
        else if (lane < 24) v = softplus_fast(m3[c * 3 + (lane - 21)]);
        else if (lane < 27) v = b0[c * 3 + (lane - 24)];
        else if (lane < 30) v = b1[c * 3 + (lane - 27)];
        else                v = b2[c * 3 + (lane - 30)];   // lanes 30,31 -> b2[0..1]
        P[lane] = v;

        float v2 = 0.0f;
        if (lane == 0)      v2 = b2[c * 3 + 2];
        else if (lane == 1) v2 = b3[c];
        else if (lane < 11) {                              // lanes 2..10 -> f values
            int k = lane - 2;                              // 0..8
            const float* fp = (k < 3) ? f0 : ((k < 6) ? f1 : f2);
            v2 = fp[c * 3 + (k % 3)];
        }
        if (lane < 11) P[32 + lane] = v2;                  // slots 32..42
        __syncwarp();

        if (lane == 0) {
            int aff = 1;
            #pragma unroll
            for (int i = 34; i < 43; i++) if (P[i] != 0.0f) aff = 0;

            // Affine collapse: logit(x) = a*x + d
            float v1a[3], u1a[3], v2a[3], u2a[3];
            #pragma unroll
            for (int oo = 0; oo < 3; oo++) {
                v1a[oo] = P[3+oo*3+0]*P[0]  + P[3+oo*3+1]*P[1]  + P[3+oo*3+2]*P[2];
                u1a[oo] = P[3+oo*3+0]*P[24] + P[3+oo*3+1]*P[25] + P[3+oo*3+2]*P[26] + P[27+oo];
            }
            #pragma unroll
            for (int oo = 0; oo < 3; oo++) {
                v2a[oo] = P[12+oo*3+0]*v1a[0] + P[12+oo*3+1]*v1a[1] + P[12+oo*3+2]*v1a[2];
                u2a[oo] = P[12+oo*3+0]*u1a[0] + P[12+oo*3+1]*u1a[1] + P[12+oo*3+2]*u1a[2] + P[30+oo];
            }
            float a = P[21]*v2a[0] + P[22]*v2a[1] + P[23]*v2a[2];
            float d = P[21]*u2a[0] + P[22]*u2a[1] + P[23]*u2a[2] + P[33];

            sC = make_float4(-a * LOG2E,
                             -(0.5f * a + d) * LOG2E,
                             __expf(a),
                             aff ? 1.0f : 0.0f);
        }
    }
    __syncthreads();

    const float4 cc = sC;
    const float na = cc.x, nd = cc.y, ea = cc.z;

    if (cc.w != 0.0f) {
        float in[8] = {zz0.x, zz0.y, zz0.z, zz0.w, zz1.x, zz1.y, zz1.z, zz1.w};
        float oh[8], ol[8];
        #pragma unroll
        for (int i = 0; i < 8; i++) {
            float h   = rintf(in[i]);
            float e1  = ex2_approx(fmaf(na, h, nd));
            float e2  = e1 * ea;
            float num = e2 - e1;
            float den = (1.0f + e1) * (1.0f + e2);
            oh[i] = h;
            ol[i] = fmaxf(num * rcp_approx(den), 1e-9f);
        }
        o[n4]            = make_float4(oh[0], oh[1], oh[2], oh[3]);
        o[n4 + 256]      = make_float4(oh[4], oh[5], oh[6], oh[7]);
        o[n4 + N4]       = make_float4(ol[0], ol[1], ol[2], ol[3]);
        o[n4 + N4 + 256] = make_float4(ol[4], ol[5], ol[6], ol[7]);
    } else {
        float4 zh0, lk0, zh1, lk1;
        fp_fallback(P, zz0, &zh0, &lk0);
        fp_fallback(P, zz1, &zh1, &lk1);
        o[n4]            = zh0;
        o[n4 + 256]      = zh1;
        o[n4 + N4]       = lk0;
        o[n4 + N4 + 256] = lk1;
    }
}

extern "C" void kernel_launch(void* const* d_in, const int* in_sizes, int n_in,
                              void* d_out, int out_size) {
    const float* z  = (const float*)d_in[0];
    const float* m0 = (const float*)d_in[1];
    const float* m1 = (const float*)d_in[2];
    const float* m2 = (const float*)d_in[3];
    const float* m3 = (const float*)d_in[4];
    const float* b0 = (const float*)d_in[5];
    const float* b1 = (const float*)d_in[6];
    const float* b2 = (const float*)d_in[7];
    const float* b3 = (const float*)d_in[8];
    const float* f0 = (const float*)d_in[9];
    const float* f1 = (const float*)d_in[10];
    const float* f2 = (const float*)d_in[11];

    const int nblocks = N4 / 512;  // 12288
    fp_fused<<<nblocks, 256>>>(z, (float*)d_out,
                               m0, m1, m2, m3, b0, b1, b2, b3, f0, f1, f2);
}

// round 12
// speedup vs baseline: 1.1777x; 1.1777x over previous
#include <cuda_runtime.h>
#include <math.h>

// Problem dims
#define BATCH 32
#define CCH   192
#define HW    4096                 // 64*64
#define NTOT  (BATCH * CCH * HW)   // 25,165,824 elements
#define N4    (NTOT / 4)           // float4 count (6,291,456)
#define LOG2E 1.4426950408889634f

// Per-channel constants packed: {na, nd, ea, affine_flag_as_float}
__device__ float4 g_c4[CCH];
// Full processed params for generic fallback path:
// [0:3)=sp0 [3:12)=W1 [12:21)=W2 [21:24)=w3
// [24:27)=b0 [27:30)=b1 [30:33)=b2 [33]=b3 [34:43)=tanh(f0..f2)
__device__ float g_full[CCH][48];

__device__ __forceinline__ float softplus_fast(float x) {
    return fmaxf(x, 0.0f) + __logf(1.0f + __expf(-fabsf(x)));
}
__device__ __forceinline__ float sigmoid_acc(float x) {
    return fmaf(0.5f, tanhf(0.5f * x), 0.5f);
}
__device__ __forceinline__ float ex2_approx(float x) {
    float r; asm("ex2.approx.f32 %0, %1;" : "=f"(r) : "f"(x)); return r;
}
__device__ __forceinline__ float rcp_approx(float x) {
    float r; asm("rcp.approx.f32 %0, %1;" : "=f"(r) : "f"(x)); return r;
}

// ---------------------------------------------------------------------------
// Precompute: one warp per channel; lane-parallel transcendentals, lane-0
// affine collapse. Publishes results then triggers the dependent launch.
// ---------------------------------------------------------------------------
__global__ void __launch_bounds__(32)
fp_precompute(const float* __restrict__ m0, const float* __restrict__ m1,
              const float* __restrict__ m2, const float* __restrict__ m3,
              const float* __restrict__ b0, const float* __restrict__ b1,
              const float* __restrict__ b2, const float* __restrict__ b3,
              const float* __restrict__ f0, const float* __restrict__ f1,
              const float* __restrict__ f2) {
    __shared__ float P[48];
    const int c = blockIdx.x;
    const int t = threadIdx.x;

    // lane-parallel param processing (t -> P slot)
    if (t < 3)        P[t]  = softplus_fast(m0[c * 3 + t]);
    else if (t < 12)  P[t]  = softplus_fast(m1[c * 9 + (t - 3)]);
    else if (t < 21)  P[t]  = softplus_fast(m2[c * 9 + (t - 12)]);
    else if (t < 24)  P[t]  = softplus_fast(m3[c * 3 + (t - 21)]);
    else if (t < 27)  P[t]  = b0[c * 3 + (t - 24)];
    else if (t < 30)  P[t]  = b1[c * 3 + (t - 27)];
    if (t < 3)        P[30 + t] = b2[c * 3 + t];
    if (t == 3)       P[33]     = b3[c];
    if (t < 3)        P[34 + t] = tanhf(f0[c * 3 + t]);
    else if (t < 6)   P[37 + (t - 3)] = tanhf(f1[c * 3 + (t - 3)]);
    else if (t < 9)   P[40 + (t - 6)] = tanhf(f2[c * 3 + (t - 6)]);
    __syncwarp();

    if (t == 0) {
        int aff = 1;
        #pragma unroll
        for (int i = 34; i < 43; i++) if (P[i] != 0.0f) aff = 0;

        // Affine collapse: logit(x) = a*x + d
        float v1[3], u1[3], v2[3], u2[3];
        #pragma unroll
        for (int o = 0; o < 3; o++) {
            v1[o] = P[3+o*3+0]*P[0]  + P[3+o*3+1]*P[1]  + P[3+o*3+2]*P[2];
            u1[o] = P[3+o*3+0]*P[24] + P[3+o*3+1]*P[25] + P[3+o*3+2]*P[26] + P[27 + o];
        }
        #pragma unroll
        for (int o = 0; o < 3; o++) {
            v2[o] = P[12+o*3+0]*v1[0] + P[12+o*3+1]*v1[1] + P[12+o*3+2]*v1[2];
            u2[o] = P[12+o*3+0]*u1[0] + P[12+o*3+1]*u1[1] + P[12+o*3+2]*u1[2] + P[30 + o];
        }
        float a = P[21]*v2[0] + P[22]*v2[1] + P[23]*v2[2];
        float d = P[21]*u2[0] + P[22]*u2[1] + P[23]*u2[2] + P[33];

        g_c4[c] = make_float4(-a * LOG2E,
                              -(0.5f * a + d) * LOG2E,
                              __expf(a),
                              aff ? 1.0f : 0.0f);
    }
    __syncwarp();
    if (t < 48) g_full[c][t] = P[t];

    // Make results visible, then allow the dependent grid to start.
    __threadfence();
#if __CUDA_ARCH__ >= 900
    cudaTriggerProgrammaticLaunchCompletion();
#endif
}

// Generic full-MLP CDF (fallback for nonzero factors)
__device__ float cdf_full(const float* __restrict__ P, float x) {
    float v[3], w[3];
    #pragma unroll
    for (int o = 0; o < 3; o++) {
        v[o] = fmaf(P[0 + o], x, P[24 + o]);
        v[o] = fmaf(P[34 + o], tanhf(v[o]), v[o]);
    }
    #pragma unroll
    for (int o = 0; o < 3; o++) {
        w[o] = P[27 + o] + P[3 + o*3 + 0]*v[0] + P[3 + o*3 + 1]*v[1] + P[3 + o*3 + 2]*v[2];
        w[o] = fmaf(P[37 + o], tanhf(w[o]), w[o]);
    }
    #pragma unroll
    for (int o = 0; o < 3; o++) {
        v[o] = P[30 + o] + P[12 + o*3 + 0]*w[0] + P[12 + o*3 + 1]*w[1] + P[12 + o*3 + 2]*w[2];
        v[o] = fmaf(P[40 + o], tanhf(v[o]), v[o]);
    }
    float s = P[33] + P[21]*v[0] + P[22]*v[1] + P[23]*v[2];
    return sigmoid_acc(s);
}

__device__ __noinline__ void fp_fallback(int c, int tid, const float4 zz,
                                         float4* zh_out, float4* lk_out) {
    __shared__ float P[48];
    if (tid < 48) P[tid] = g_full[c][tid];
    __syncthreads();
    float in[4] = {zz.x, zz.y, zz.z, zz.w};
    float oh[4], ol[4];
    #pragma unroll
    for (int i = 0; i < 4; i++) {
        float h  = rintf(in[i]);
        float up = cdf_full(P, h + 0.5f);
        float lo = cdf_full(P, h - 0.5f);
        oh[i] = h;
        ol[i] = fmaxf(up - lo, 1e-9f);
    }
    *zh_out = make_float4(oh[0], oh[1], oh[2], oh[3]);
    *lk_out = make_float4(ol[0], ol[1], ol[2], ol[3]);
}

// ---------------------------------------------------------------------------
// Main kernel (PDL secondary): issue the 2 streaming z loads FIRST, then
// cudaGridDependencySynchronize() (waits for precompute's trigger), then the
// 11-inst/element affine hot path. 8 elems/thread; 2 blocks per (b,c) slice.
// Per element:
//   h   = rint(z)                               (half-to-even == jnp.round)
//   e1  = 2^(na*h + nd)   == exp(-(a*(h+0.5)+d))
//   e2  = e1 * ea         == exp(-(logit - a))
//   lik = max((e2-e1) * rcp((1+e1)*(1+e2)), 1e-9)
// Tails: e1->inf => NaN => fmax -> 1e-9 (== clipped ref); e1->0 => 0 -> 1e-9.
// ---------------------------------------------------------------------------
__global__ void __launch_bounds__(256)
fp_main(const float* __restrict__ z, float* __restrict__ out) {
    const int tid = threadIdx.x;
    const int c  = (blockIdx.x >> 1) % CCH;        // 2 blocks per (b,c) slice
    const int n4 = blockIdx.x * 512 + tid;         // first float4 index

    const float4* zin = reinterpret_cast<const float4*>(z);
    float4* o = reinterpret_cast<float4*>(out);

    // Independent of precompute results — issue before the dependency wait.
    float4 zz0 = __ldcs(zin + n4);
    float4 zz1 = __ldcs(zin + n4 + 256);

#if __CUDA_ARCH__ >= 900
    cudaGridDependencySynchronize();
#endif

    const float4 cc = g_c4[c];
    const float na = cc.x, nd = cc.y, ea = cc.z;

    if (cc.w != 0.0f) {
        float in[8] = {zz0.x, zz0.y, zz0.z, zz0.w, zz1.x, zz1.y, zz1.z, zz1.w};
        float oh[8], ol[8];
        #pragma unroll
        for (int i = 0; i < 8; i++) {
            float h   = rintf(in[i]);
            float e1  = ex2_approx(fmaf(na, h, nd));
            float e2  = e1 * ea;
            float num = e2 - e1;
            float den = (1.0f + e1) * (1.0f + e2);
            oh[i] = h;
            ol[i] = fmaxf(num * rcp_approx(den), 1e-9f);
        }
        o[n4]            = make_float4(oh[0], oh[1], oh[2], oh[3]);
        o[n4 + 256]      = make_float4(oh[4], oh[5], oh[6], oh[7]);
        o[n4 + N4]       = make_float4(ol[0], ol[1], ol[2], ol[3]);
        o[n4 + N4 + 256] = make_float4(ol[4], ol[5], ol[6], ol[7]);
    } else {
        float4 zh0, lk0, zh1, lk1;
        fp_fallback(c, tid, zz0, &zh0, &lk0);
        fp_fallback(c, tid, zz1, &zh1, &lk1);
        o[n4]            = zh0;
        o[n4 + 256]      = zh1;
        o[n4 + N4]       = lk0;
        o[n4 + N4 + 256] = lk1;
    }
}

extern "C" void kernel_launch(void* const* d_in, const int* in_sizes, int n_in,
                              void* d_out, int out_size) {
    const float* z  = (const float*)d_in[0];
    const float* m0 = (const float*)d_in[1];
    const float* m1 = (const float*)d_in[2];
    const float* m2 = (const float*)d_in[3];
    const float* m3 = (const float*)d_in[4];
    const float* b0 = (const float*)d_in[5];
    const float* b1 = (const float*)d_in[6];
    const float* b2 = (const float*)d_in[7];
    const float* b3 = (const float*)d_in[8];
    const float* f0 = (const float*)d_in[9];
    const float* f1 = (const float*)d_in[10];
    const float* f2 = (const float*)d_in[11];

    fp_precompute<<<CCH, 32>>>(m0, m1, m2, m3, b0, b1, b2, b3, f0, f1, f2);

    // Launch fp_main as a PDL secondary: its prologue + z loads overlap the
    // precompute kernel's execution; griddepsync provides the data ordering.
    const int nblocks = N4 / 512;  // 12288
    cudaLaunchConfig_t cfg = {};
    cfg.gridDim  = dim3(nblocks, 1, 1);
    cfg.blockDim = dim3(256, 1, 1);
    cudaLaunchAttribute attrs[1];
    attrs[0].id = cudaLaunchAttributeProgrammaticStreamSerialization;
    attrs[0].val.programmaticStreamSerializationAllowed = 1;
    cfg.attrs = attrs;
    cfg.numAttrs = 1;
    cudaError_t err = cudaLaunchKernelEx(&cfg, fp_main, z, (float*)d_out);
    if (err != cudaSuccess) {
        // Fallback: plain launch (normal stream ordering, still correct).
        fp_main<<<nblocks, 256>>>(z, (float*)d_out);
    }
}